// round 2
// baseline (speedup 1.0000x reference)
#include <cuda_runtime.h>
#include <math.h>

// Problem constants (fixed by the dataset):
// B=2, N=2048 -> T=4096 tokens, D=1024, E=8 experts, H=2048, K=2 (top-k)
#define Tn 4096
#define Dd 1024
#define Ee 8
#define Hh 2048

// ---------------- device scratch (allocation-free rule: __device__ globals) --
__device__ int   g_cnt[Ee];                         // tokens routed to each expert
__device__ int   g_list[Ee * Tn];                   // per-expert list of pair slots (= token*2 + k)
__device__ float g_gate[Tn * 2];                    // gate value per (token, k)
__device__ float g_ent[Tn];                         // per-token entropy
__device__ float g_h[(size_t)Ee * Tn * Hh];         // hidden activations, 256 MB
__device__ float g_y[(size_t)Tn * 2 * Dd];          // per-pair expert outputs, 32 MB

// ---------------------------------------------------------------- init ------
__global__ void init_kernel() {
    if (threadIdx.x < Ee) g_cnt[threadIdx.x] = 0;
}

// ------------------------------------------------------------- routing ------
// One warp per token: logits = x_t @ w_gate + b_gate (E=8), top-2, softmax,
// per-token entropy, and append (token,k) to the chosen experts' lists.
__global__ void routing_kernel(const float* __restrict__ x,
                               const float* __restrict__ wg,
                               const float* __restrict__ bg) {
    const int t    = blockIdx.x * 8 + (threadIdx.x >> 5);
    const int lane = threadIdx.x & 31;
    if (t >= Tn) return;

    float acc[Ee];
#pragma unroll
    for (int e = 0; e < Ee; e++) acc[e] = 0.f;

    const float* xr = x + (size_t)t * Dd;
    for (int c = lane; c < Dd; c += 32) {
        const float xv = xr[c];
        const float4* w4 = reinterpret_cast<const float4*>(wg + (size_t)c * Ee);
        const float4 a = w4[0];
        const float4 b = w4[1];
        acc[0] += xv * a.x; acc[1] += xv * a.y; acc[2] += xv * a.z; acc[3] += xv * a.w;
        acc[4] += xv * b.x; acc[5] += xv * b.y; acc[6] += xv * b.z; acc[7] += xv * b.w;
    }
#pragma unroll
    for (int off = 16; off; off >>= 1) {
#pragma unroll
        for (int e = 0; e < Ee; e++)
            acc[e] += __shfl_xor_sync(0xffffffffu, acc[e], off);
    }

    if (lane == 0) {
        float l[Ee];
#pragma unroll
        for (int e = 0; e < Ee; e++) l[e] = acc[e] + bg[e];

        // top-2 (ties -> lowest index, matching jax.lax.top_k)
        int i0 = 0; float v0 = l[0];
#pragma unroll
        for (int e = 1; e < Ee; e++) if (l[e] > v0) { v0 = l[e]; i0 = e; }
        int i1 = -1; float v1 = -3.4e38f;
#pragma unroll
        for (int e = 0; e < Ee; e++)
            if (e != i0 && l[e] > v1) { v1 = l[e]; i1 = e; }

        // softmax over the two selected logits (v0 >= v1)
        const float e1 = expf(v1 - v0);
        const float inv = 1.f / (1.f + e1);
        const float gv0 = inv;
        const float gv1 = e1 * inv;

        g_ent[t] = -(gv0 * logf(fmaxf(gv0, 1e-8f)) +
                     gv1 * logf(fmaxf(gv1, 1e-8f)));

        int p0 = atomicAdd(&g_cnt[i0], 1);
        g_list[i0 * Tn + p0] = t * 2 + 0;
        g_gate[t * 2 + 0] = gv0;

        int p1 = atomicAdd(&g_cnt[i1], 1);
        g_list[i1 * Tn + p1] = t * 2 + 1;
        g_gate[t * 2 + 1] = gv1;
    }
}

// ------------------------------------------------- entropy (deterministic) --
__global__ void entropy_kernel(float* __restrict__ out, int do_write) {
    __shared__ float sh[1024];
    const int t = threadIdx.x;
    float s = 0.f;
    for (int i = t; i < Tn; i += 1024) s += g_ent[i];
    sh[t] = s;
    __syncthreads();
    for (int o = 512; o; o >>= 1) {
        if (t < o) sh[t] += sh[t + o];
        __syncthreads();
    }
    if (t == 0 && do_write) out[(size_t)Tn * Dd] = sh[0] / (float)Tn;
}

// -------------------------------------------------------------- GEMM 1 ------
// h[e, r, :] = relu( x[token(r), :] @ w1[e] + b1[e] ), rows gathered per expert.
// 128x128 tile, BK=16, 8x8 per-thread microtile, 256 threads.
__global__ __launch_bounds__(256, 1)
void gemm1_kernel(const float* __restrict__ x,
                  const float* __restrict__ w1,
                  const float* __restrict__ b1) {
    const int e    = blockIdx.z;
    const int cnt  = g_cnt[e];
    const int row0 = blockIdx.x * 128;
    if (row0 >= cnt) return;
    const int col0 = blockIdx.y * 128;

    __shared__ float As[16][132];   // padded: 132*4B = 528B row stride (16B aligned)
    __shared__ float Bs[16][128];

    const int tid = threadIdx.x;
    const int tx  = tid & 15;       // 16 col groups
    const int ty  = tid >> 4;       // 16 row groups

    // A-tile load mapping: 512 float4 vectors (128 rows x 4), 2 per thread
    const int arow0 = tid >> 2;           // 0..63
    const int arow1 = arow0 + 64;         // 64..127
    const int akc   = tid & 3;            // which float4 within 16-wide k-strip
    int tok0 = -1, tok1 = -1;
    if (row0 + arow0 < cnt) tok0 = g_list[e * Tn + row0 + arow0] >> 1;
    if (row0 + arow1 < cnt) tok1 = g_list[e * Tn + row0 + arow1] >> 1;

    // B-tile load mapping: 512 float4 vectors (16 rows x 32), 2 per thread
    const int bk0 = tid >> 5;             // 0..7
    const int bk1 = bk0 + 8;              // 8..15
    const int bc  = tid & 31;

    const float* w1e = w1 + (size_t)e * Dd * Hh;

    float acc[8][8];
#pragma unroll
    for (int i = 0; i < 8; i++)
#pragma unroll
        for (int j = 0; j < 8; j++) acc[i][j] = 0.f;

    for (int k0 = 0; k0 < Dd; k0 += 16) {
        float4 a0 = make_float4(0.f, 0.f, 0.f, 0.f), a1 = a0;
        if (tok0 >= 0) a0 = *(const float4*)(x + (size_t)tok0 * Dd + k0 + akc * 4);
        if (tok1 >= 0) a1 = *(const float4*)(x + (size_t)tok1 * Dd + k0 + akc * 4);
        const float4 b0 = *(const float4*)(w1e + (size_t)(k0 + bk0) * Hh + col0 + bc * 4);
        const float4 b1v = *(const float4*)(w1e + (size_t)(k0 + bk1) * Hh + col0 + bc * 4);

        __syncthreads();
        As[akc * 4 + 0][arow0] = a0.x;
        As[akc * 4 + 1][arow0] = a0.y;
        As[akc * 4 + 2][arow0] = a0.z;
        As[akc * 4 + 3][arow0] = a0.w;
        As[akc * 4 + 0][arow1] = a1.x;
        As[akc * 4 + 1][arow1] = a1.y;
        As[akc * 4 + 2][arow1] = a1.z;
        As[akc * 4 + 3][arow1] = a1.w;
        *(float4*)&Bs[bk0][bc * 4] = b0;
        *(float4*)&Bs[bk1][bc * 4] = b1v;
        __syncthreads();

#pragma unroll
        for (int kk = 0; kk < 16; kk++) {
            const float4 ar0 = *(const float4*)&As[kk][ty * 8];
            const float4 ar1 = *(const float4*)&As[kk][ty * 8 + 4];
            const float4 br0 = *(const float4*)&Bs[kk][tx * 8];
            const float4 br1 = *(const float4*)&Bs[kk][tx * 8 + 4];
            const float av[8] = {ar0.x, ar0.y, ar0.z, ar0.w, ar1.x, ar1.y, ar1.z, ar1.w};
            const float bv[8] = {br0.x, br0.y, br0.z, br0.w, br1.x, br1.y, br1.z, br1.w};
#pragma unroll
            for (int i = 0; i < 8; i++)
#pragma unroll
                for (int j = 0; j < 8; j++) acc[i][j] += av[i] * bv[j];
        }
    }

    const float* bp = b1 + (size_t)e * Hh + col0 + tx * 8;
    float bias[8];
#pragma unroll
    for (int j = 0; j < 8; j++) bias[j] = bp[j];

#pragma unroll
    for (int i = 0; i < 8; i++) {
        const int r = row0 + ty * 8 + i;
        if (r >= cnt) continue;
        float* hp = g_h + ((size_t)e * Tn + r) * Hh + col0 + tx * 8;
        float4 o0, o1;
        o0.x = fmaxf(acc[i][0] + bias[0], 0.f);
        o0.y = fmaxf(acc[i][1] + bias[1], 0.f);
        o0.z = fmaxf(acc[i][2] + bias[2], 0.f);
        o0.w = fmaxf(acc[i][3] + bias[3], 0.f);
        o1.x = fmaxf(acc[i][4] + bias[4], 0.f);
        o1.y = fmaxf(acc[i][5] + bias[5], 0.f);
        o1.z = fmaxf(acc[i][6] + bias[6], 0.f);
        o1.w = fmaxf(acc[i][7] + bias[7], 0.f);
        *(float4*)hp = o0;
        *(float4*)(hp + 4) = o1;
    }
}

// -------------------------------------------------------------- GEMM 2 ------
// y[pair_slot(r), :] = h[e, r, :] @ w2[e] + b2[e]
__global__ __launch_bounds__(256, 1)
void gemm2_kernel(const float* __restrict__ w2,
                  const float* __restrict__ b2) {
    const int e    = blockIdx.z;
    const int cnt  = g_cnt[e];
    const int row0 = blockIdx.x * 128;
    if (row0 >= cnt) return;
    const int col0 = blockIdx.y * 128;

    __shared__ float As[16][132];
    __shared__ float Bs[16][128];

    const int tid = threadIdx.x;
    const int tx  = tid & 15;
    const int ty  = tid >> 4;

    const int arow0 = tid >> 2;
    const int arow1 = arow0 + 64;
    const int akc   = tid & 3;
    const bool v0 = (row0 + arow0 < cnt);
    const bool v1 = (row0 + arow1 < cnt);
    const float* h0 = g_h + ((size_t)e * Tn + row0 + arow0) * Hh;
    const float* h1 = g_h + ((size_t)e * Tn + row0 + arow1) * Hh;

    const int bk0 = tid >> 5;
    const int bk1 = bk0 + 8;
    const int bc  = tid & 31;

    const float* w2e = w2 + (size_t)e * Hh * Dd;

    float acc[8][8];
#pragma unroll
    for (int i = 0; i < 8; i++)
#pragma unroll
        for (int j = 0; j < 8; j++) acc[i][j] = 0.f;

    for (int k0 = 0; k0 < Hh; k0 += 16) {
        float4 a0 = make_float4(0.f, 0.f, 0.f, 0.f), a1 = a0;
        if (v0) a0 = *(const float4*)(h0 + k0 + akc * 4);
        if (v1) a1 = *(const float4*)(h1 + k0 + akc * 4);
        const float4 b0 = *(const float4*)(w2e + (size_t)(k0 + bk0) * Dd + col0 + bc * 4);
        const float4 b1v = *(const float4*)(w2e + (size_t)(k0 + bk1) * Dd + col0 + bc * 4);

        __syncthreads();
        As[akc * 4 + 0][arow0] = a0.x;
        As[akc * 4 + 1][arow0] = a0.y;
        As[akc * 4 + 2][arow0] = a0.z;
        As[akc * 4 + 3][arow0] = a0.w;
        As[akc * 4 + 0][arow1] = a1.x;
        As[akc * 4 + 1][arow1] = a1.y;
        As[akc * 4 + 2][arow1] = a1.z;
        As[akc * 4 + 3][arow1] = a1.w;
        *(float4*)&Bs[bk0][bc * 4] = b0;
        *(float4*)&Bs[bk1][bc * 4] = b1v;
        __syncthreads();

#pragma unroll
        for (int kk = 0; kk < 16; kk++) {
            const float4 ar0 = *(const float4*)&As[kk][ty * 8];
            const float4 ar1 = *(const float4*)&As[kk][ty * 8 + 4];
            const float4 br0 = *(const float4*)&Bs[kk][tx * 8];
            const float4 br1 = *(const float4*)&Bs[kk][tx * 8 + 4];
            const float av[8] = {ar0.x, ar0.y, ar0.z, ar0.w, ar1.x, ar1.y, ar1.z, ar1.w};
            const float bv[8] = {br0.x, br0.y, br0.z, br0.w, br1.x, br1.y, br1.z, br1.w};
#pragma unroll
            for (int i = 0; i < 8; i++)
#pragma unroll
                for (int j = 0; j < 8; j++) acc[i][j] += av[i] * bv[j];
        }
    }

    const float* bp = b2 + (size_t)e * Dd + col0 + tx * 8;
    float bias[8];
#pragma unroll
    for (int j = 0; j < 8; j++) bias[j] = bp[j];

#pragma unroll
    for (int i = 0; i < 8; i++) {
        const int r = row0 + ty * 8 + i;
        if (r >= cnt) continue;
        const int slot = g_list[e * Tn + r];            // token*2 + k
        float* yp = g_y + (size_t)slot * Dd + col0 + tx * 8;
        float4 o0, o1;
        o0.x = acc[i][0] + bias[0];
        o0.y = acc[i][1] + bias[1];
        o0.z = acc[i][2] + bias[2];
        o0.w = acc[i][3] + bias[3];
        o1.x = acc[i][4] + bias[4];
        o1.y = acc[i][5] + bias[5];
        o1.z = acc[i][6] + bias[6];
        o1.w = acc[i][7] + bias[7];
        *(float4*)yp = o0;
        *(float4*)(yp + 4) = o1;
    }
}

// ------------------------------------------------------ gated combine -------
// out[t, :] = g0 * y[2t, :] + g1 * y[2t+1, :]   (deterministic; no atomics)
__global__ void combine_kernel(float* __restrict__ out) {
    const int idx = blockIdx.x * 256 + threadIdx.x;   // over Tn*Dd/4 float4s
    const int t   = idx / (Dd / 4);
    const int c   = idx % (Dd / 4);
    const float gA = g_gate[2 * t];
    const float gB = g_gate[2 * t + 1];
    const float4* y4 = (const float4*)g_y;
    const float4 ya = y4[(size_t)(2 * t) * (Dd / 4) + c];
    const float4 yb = y4[(size_t)(2 * t + 1) * (Dd / 4) + c];
    float4 o;
    o.x = gA * ya.x + gB * yb.x;
    o.y = gA * ya.y + gB * yb.y;
    o.z = gA * ya.z + gB * yb.z;
    o.w = gA * ya.w + gB * yb.w;
    ((float4*)out)[idx] = o;
}

// ---------------------------------------------------------------- launch ----
extern "C" void kernel_launch(void* const* d_in, const int* in_sizes, int n_in,
                              void* d_out, int out_size) {
    const float* x  = (const float*)d_in[0];   // (B,N,D)
    const float* wg = (const float*)d_in[1];   // (D,E)
    const float* bg = (const float*)d_in[2];   // (E,)
    const float* w1 = (const float*)d_in[3];   // (E,D,H)
    const float* b1 = (const float*)d_in[4];   // (E,H)
    const float* w2 = (const float*)d_in[5];   // (E,H,D)
    const float* b2 = (const float*)d_in[6];   // (E,D)
    float* out = (float*)d_out;

    init_kernel<<<1, 32>>>();
    routing_kernel<<<Tn / 8, 256>>>(x, wg, bg);
    entropy_kernel<<<1, 1024>>>(out, (out_size > Tn * Dd) ? 1 : 0);
    gemm1_kernel<<<dim3(Tn / 128, Hh / 128, Ee), 256>>>(x, w1, b1);
    gemm2_kernel<<<dim3(Tn / 128, Dd / 128, Ee), 256>>>(w2, b2);
    combine_kernel<<<(Tn * Dd / 4) / 256, 256>>>(out);
}

// round 4
// speedup vs baseline: 2.9385x; 2.9385x over previous
#include <cuda_runtime.h>
#include <stdint.h>
#include <math.h>

// Problem constants: B=2, N=2048 -> T=4096 tokens, D=1024, E=8, H=2048, K=2
#define Tn 4096
#define Dd 1024
#define Ee 8
#define Hh 2048

// GEMM tile config
#define BM 128
#define BN 256
#define BK 16
#define STAGES 3
#define ASTR 20                      // A smem row stride (floats), conflict-free permutation
#define BSTR 264                     // B smem row stride (floats), == 8 mod 32
#define ASZ (BM * ASTR)              // 2560 floats / stage
#define BSZ (BK * BSTR)              // 4224 floats / stage
#define SMEM_FLOATS (STAGES * (ASZ + BSZ))   // 20352 floats = 81408 B

// ---------------- device scratch (allocation-free rule: __device__ globals) --
__device__ int   g_cnt[Ee];
__device__ int   g_list[Ee * Tn];            // pair slot (= token*2 + k) per expert row
__device__ float g_gate[Tn * 2];
__device__ float g_ent[Tn];
__device__ float g_h[(size_t)Ee * Tn * Hh];  // hidden activations
__device__ float g_y[(size_t)Tn * 2 * Dd];   // per-pair expert outputs

// ---------------------------------------------------------------- init ------
__global__ void init_kernel() {
    if (threadIdx.x < Ee) g_cnt[threadIdx.x] = 0;
}

// ------------------------------------------------------------- routing ------
__global__ void routing_kernel(const float* __restrict__ x,
                               const float* __restrict__ wg,
                               const float* __restrict__ bg) {
    const int t    = blockIdx.x * 8 + (threadIdx.x >> 5);
    const int lane = threadIdx.x & 31;
    if (t >= Tn) return;

    float acc[Ee];
#pragma unroll
    for (int e = 0; e < Ee; e++) acc[e] = 0.f;

    const float* xr = x + (size_t)t * Dd;
    for (int c = lane; c < Dd; c += 32) {
        const float xv = xr[c];
        const float4* w4 = reinterpret_cast<const float4*>(wg + (size_t)c * Ee);
        const float4 a = w4[0];
        const float4 b = w4[1];
        acc[0] += xv * a.x; acc[1] += xv * a.y; acc[2] += xv * a.z; acc[3] += xv * a.w;
        acc[4] += xv * b.x; acc[5] += xv * b.y; acc[6] += xv * b.z; acc[7] += xv * b.w;
    }
#pragma unroll
    for (int off = 16; off; off >>= 1) {
#pragma unroll
        for (int e = 0; e < Ee; e++)
            acc[e] += __shfl_xor_sync(0xffffffffu, acc[e], off);
    }

    if (lane == 0) {
        float l[Ee];
#pragma unroll
        for (int e = 0; e < Ee; e++) l[e] = acc[e] + bg[e];

        // top-2 (ties -> lowest index, matching jax.lax.top_k)
        int i0 = 0; float v0 = l[0];
#pragma unroll
        for (int e = 1; e < Ee; e++) if (l[e] > v0) { v0 = l[e]; i0 = e; }
        int i1 = -1; float v1 = -3.4e38f;
#pragma unroll
        for (int e = 0; e < Ee; e++)
            if (e != i0 && l[e] > v1) { v1 = l[e]; i1 = e; }

        const float e1 = expf(v1 - v0);
        const float inv = 1.f / (1.f + e1);
        const float gv0 = inv;
        const float gv1 = e1 * inv;

        g_ent[t] = -(gv0 * logf(fmaxf(gv0, 1e-8f)) +
                     gv1 * logf(fmaxf(gv1, 1e-8f)));

        int p0 = atomicAdd(&g_cnt[i0], 1);
        g_list[i0 * Tn + p0] = t * 2 + 0;
        g_gate[t * 2 + 0] = gv0;

        int p1 = atomicAdd(&g_cnt[i1], 1);
        g_list[i1 * Tn + p1] = t * 2 + 1;
        g_gate[t * 2 + 1] = gv1;
    }
}

// ------------------------------------------------- entropy (deterministic) --
__global__ void entropy_kernel(float* __restrict__ out, int do_write) {
    __shared__ float sh[1024];
    const int t = threadIdx.x;
    float s = 0.f;
    for (int i = t; i < Tn; i += 1024) s += g_ent[i];
    sh[t] = s;
    __syncthreads();
    for (int o = 512; o; o >>= 1) {
        if (t < o) sh[t] += sh[t + o];
        __syncthreads();
    }
    if (t == 0 && do_write) out[(size_t)Tn * Dd] = sh[0] / (float)Tn;
}

// ---------------------------------------------------------- tf32 helpers ----
__device__ __forceinline__ void cp16(float* s, const float* g) {
    uint32_t sa = (uint32_t)__cvta_generic_to_shared(s);
    asm volatile("cp.async.cg.shared.global [%0], [%1], 16;" :: "r"(sa), "l"(g));
}
__device__ __forceinline__ uint32_t f2tf(float x) {
    uint32_t r;
    asm volatile("cvt.rna.tf32.f32 %0, %1;" : "=r"(r) : "f"(x));
    return r;
}
__device__ __forceinline__ void mma8(float* c, const uint32_t* a, const uint32_t* b) {
    asm volatile(
        "mma.sync.aligned.m16n8k8.row.col.f32.tf32.tf32.f32 "
        "{%0,%1,%2,%3}, {%4,%5,%6,%7}, {%8,%9}, {%0,%1,%2,%3};"
        : "+f"(c[0]), "+f"(c[1]), "+f"(c[2]), "+f"(c[3])
        : "r"(a[0]), "r"(a[1]), "r"(a[2]), "r"(a[3]), "r"(b[0]), "r"(b[1]));
}

// ----------------------------------------------------- tf32 grouped GEMM ----
// C[r, col] = A[r, :] @ W_e[:, col] + bias_e[col]   (relu + gather if G1,
// scatter-to-pair-slot if !G1). Block tile 128x256, BK=16, 8 warps (2m x 4n),
// warp tile 64x64, 3-stage cp.async pipeline.
template<int N, int KD, bool G1>
__global__ __launch_bounds__(256, 1)
void moe_gemm(const float* __restrict__ x,
              const float* __restrict__ W,
              const float* __restrict__ bias)
{
    const int e    = blockIdx.z;
    const int cnt  = g_cnt[e];
    const int row0 = blockIdx.x * BM;
    if (row0 >= cnt) return;
    const int col0 = blockIdx.y * BN;

    extern __shared__ float sm[];
    float* As = sm;                    // [STAGES][BM][ASTR]
    float* Bs = sm + STAGES * ASZ;     // [STAGES][BK][BSTR]

    const int tid  = threadIdx.x;
    const int lane = tid & 31;
    const int warp = tid >> 5;
    const int wm   = warp & 1;         // 2 warps along M
    const int wn   = warp >> 1;        // 4 warps along N

    // --- A loader: 2 rows per thread (128 rows x 4 float4 per stage) ---
    const int ar0 = tid >> 2;          // 0..63
    const int ak4 = (tid & 3) * 4;     // k offset within BK (0,4,8,12)
    const float* ap0;
    const float* ap1;
    if (G1) {
        // gather token rows; g_list entries are always valid slot ids (<= 8191)
        const int t0 = g_list[e * Tn + row0 + ar0] >> 1;
        const int t1 = g_list[e * Tn + row0 + ar0 + 64] >> 1;
        ap0 = x + (size_t)t0 * KD + ak4;
        ap1 = x + (size_t)t1 * KD + ak4;
    } else {
        ap0 = g_h + ((size_t)e * Tn + row0 + ar0) * KD + ak4;
        ap1 = g_h + ((size_t)e * Tn + row0 + ar0 + 64) * KD + ak4;
    }

    // --- B loader: 4 float4 per thread (16 rows x 64 float4 per stage) ---
    const int brow = tid >> 6;         // 0..3
    const int bc4  = (tid & 63) * 4;   // 0..252
    const float* Wp = W + (size_t)e * KD * N + col0 + bc4;

    float acc[4][8][4];
#pragma unroll
    for (int mi = 0; mi < 4; mi++)
#pragma unroll
        for (int ni = 0; ni < 8; ni++)
#pragma unroll
            for (int j = 0; j < 4; j++) acc[mi][ni][j] = 0.f;

    auto load_stage = [&](int s, int kt) {
        float* as = As + s * ASZ;
        float* bs = Bs + s * BSZ;
        const int kg = kt * BK;
        cp16(as + ar0 * ASTR + ak4, ap0 + kg);
        cp16(as + (ar0 + 64) * ASTR + ak4, ap1 + kg);
#pragma unroll
        for (int j = 0; j < 4; j++)
            cp16(bs + (brow + j * 4) * BSTR + bc4,
                 Wp + (size_t)(kg + brow + j * 4) * N);
    };

    auto compute = [&](int s) {
        const float* as = As + s * ASZ;
        const float* bs = Bs + s * BSZ;
#pragma unroll
        for (int g = 0; g < 2; g++) {              // two k8 steps per BK=16
            uint32_t Af[4][4];
#pragma unroll
            for (int mi = 0; mi < 4; mi++) {
                const int r = wm * 64 + mi * 16 + (lane >> 2);
                const int k = g * 8 + (lane & 3);
                const float* p = as + r * ASTR + k;
                Af[mi][0] = f2tf(p[0]);            // (r,   k)
                Af[mi][1] = f2tf(p[8 * ASTR]);     // (r+8, k)
                Af[mi][2] = f2tf(p[4]);            // (r,   k+4)
                Af[mi][3] = f2tf(p[8 * ASTR + 4]); // (r+8, k+4)
            }
            uint32_t Bf[8][2];
#pragma unroll
            for (int ni = 0; ni < 8; ni++) {
                const int c = wn * 64 + ni * 8 + (lane >> 2);
                const int k = g * 8 + (lane & 3);
                const float* p = bs + k * BSTR + c;
                Bf[ni][0] = f2tf(p[0]);            // (k,   c)
                Bf[ni][1] = f2tf(p[4 * BSTR]);     // (k+4, c)
            }
#pragma unroll
            for (int mi = 0; mi < 4; mi++)
#pragma unroll
                for (int ni = 0; ni < 8; ni++)
                    mma8(acc[mi][ni], Af[mi], Bf[ni]);
        }
    };

    constexpr int KT = KD / BK;
#pragma unroll
    for (int s = 0; s < STAGES - 1; s++) {
        load_stage(s, s);
        asm volatile("cp.async.commit_group;");
    }
    for (int kt = 0; kt < KT; kt++) {
        asm volatile("cp.async.wait_group 1;" ::: "memory");
        __syncthreads();
        const int nt = kt + STAGES - 1;
        if (nt < KT) load_stage(nt % STAGES, nt);
        asm volatile("cp.async.commit_group;");
        compute(kt % STAGES);
    }

    // ------------------------------- epilogue -------------------------------
    const float* bp = bias + (size_t)e * N + col0;
    float2 bv[8];
#pragma unroll
    for (int ni = 0; ni < 8; ni++) {
        const int c = wn * 64 + ni * 8 + 2 * (lane & 3);
        bv[ni] = *(const float2*)(bp + c);
    }
#pragma unroll
    for (int mi = 0; mi < 4; mi++) {
#pragma unroll
        for (int h = 0; h < 2; h++) {
            const int r = row0 + wm * 64 + mi * 16 + (lane >> 2) + h * 8;
            if (r >= cnt) continue;
            float* op;
            if (G1) {
                op = g_h + ((size_t)e * Tn + r) * N;      // N == Hh
            } else {
                const int slot = g_list[e * Tn + r];      // token*2 + k
                op = g_y + (size_t)slot * N;              // N == Dd
            }
#pragma unroll
            for (int ni = 0; ni < 8; ni++) {
                const int c = col0 + wn * 64 + ni * 8 + 2 * (lane & 3);
                float v0 = acc[mi][ni][h * 2 + 0] + bv[ni].x;
                float v1 = acc[mi][ni][h * 2 + 1] + bv[ni].y;
                if (G1) { v0 = fmaxf(v0, 0.f); v1 = fmaxf(v1, 0.f); }
                *(float2*)(op + c) = make_float2(v0, v1);
            }
        }
    }
}

// ------------------------------------------------------ gated combine -------
__global__ void combine_kernel(float* __restrict__ out) {
    const int idx = blockIdx.x * 256 + threadIdx.x;
    const int t   = idx / (Dd / 4);
    const int c   = idx % (Dd / 4);
    const float gA = g_gate[2 * t];
    const float gB = g_gate[2 * t + 1];
    const float4* y4 = (const float4*)g_y;
    const float4 ya = y4[(size_t)(2 * t) * (Dd / 4) + c];
    const float4 yb = y4[(size_t)(2 * t + 1) * (Dd / 4) + c];
    float4 o;
    o.x = gA * ya.x + gB * yb.x;
    o.y = gA * ya.y + gB * yb.y;
    o.z = gA * ya.z + gB * yb.z;
    o.w = gA * ya.w + gB * yb.w;
    ((float4*)out)[idx] = o;
}

// ---------------------------------------------------------------- launch ----
extern "C" void kernel_launch(void* const* d_in, const int* in_sizes, int n_in,
                              void* d_out, int out_size) {
    const float* x  = (const float*)d_in[0];   // (B,N,D)
    const float* wg = (const float*)d_in[1];   // (D,E)
    const float* bg = (const float*)d_in[2];   // (E,)
    const float* w1 = (const float*)d_in[3];   // (E,D,H)
    const float* b1 = (const float*)d_in[4];   // (E,H)
    const float* w2 = (const float*)d_in[5];   // (E,H,D)
    const float* b2 = (const float*)d_in[6];   // (E,D)
    float* out = (float*)d_out;

    const int smem_bytes = SMEM_FLOATS * (int)sizeof(float);   // 81408
    cudaFuncSetAttribute(moe_gemm<Hh, Dd, true>,
                         cudaFuncAttributeMaxDynamicSharedMemorySize, smem_bytes);
    cudaFuncSetAttribute(moe_gemm<Dd, Hh, false>,
                         cudaFuncAttributeMaxDynamicSharedMemorySize, smem_bytes);

    init_kernel<<<1, 32>>>();
    routing_kernel<<<Tn / 8, 256>>>(x, wg, bg);
    entropy_kernel<<<1, 1024>>>(out, (out_size > Tn * Dd) ? 1 : 0);
    moe_gemm<Hh, Dd, true><<<dim3(Tn / BM, Hh / BN, Ee), 256, smem_bytes>>>(x, w1, b1);
    moe_gemm<Dd, Hh, false><<<dim3(Tn / BM, Dd / BN, Ee), 256, smem_bytes>>>(x, w2, b2);
    combine_kernel<<<(Tn * Dd / 4) / 256, 256>>>(out);
}